// round 6
// baseline (speedup 1.0000x reference)
#include <cuda_runtime.h>
#include <cuda_bf16.h>

// out[b,t,c] = (x[b,src,c] + noise[b,src,c]*0.1f) * scale[b]
// src = (t - (shifts[b] - MAX_SHIFT)) mod T
// B=64, T=4096, C=128, fp32. HBM-streaming; v8 (256-bit) accesses + .cs hints,
// 256-thread blocks (best-occupancy config).

#define B_DIM 64
#define T_DIM 4096
#define C_DIM 128
#define MAX_SHIFT 409
#define NOISE_STD 0.1f

#define C8 (C_DIM / 8)   // 16 v8-groups per (b,t) row
#define THREADS 256

__device__ __forceinline__ void ldg256_cs(const float* p, float v[8]) {
    asm volatile("ld.global.cs.v8.f32 {%0,%1,%2,%3,%4,%5,%6,%7}, [%8];"
                 : "=f"(v[0]), "=f"(v[1]), "=f"(v[2]), "=f"(v[3]),
                   "=f"(v[4]), "=f"(v[5]), "=f"(v[6]), "=f"(v[7])
                 : "l"(p));
}

__device__ __forceinline__ void stg256_cs(float* p, const float v[8]) {
    asm volatile("st.global.cs.v8.f32 [%0], {%1,%2,%3,%4,%5,%6,%7,%8};"
                 :: "l"(p),
                    "f"(v[0]), "f"(v[1]), "f"(v[2]), "f"(v[3]),
                    "f"(v[4]), "f"(v[5]), "f"(v[6]), "f"(v[7])
                 : "memory");
}

__global__ __launch_bounds__(THREADS)
void ts_augment_kernel(const float* __restrict__ x,
                       const float* __restrict__ noise,
                       const float* __restrict__ scale,
                       const int*   __restrict__ shifts,
                       float*       __restrict__ out)
{
    // flat index over B * T * C8 = 4,194,304; grid*block covers exactly.
    unsigned idx = blockIdx.x * blockDim.x + threadIdx.x;
    unsigned c8 = idx & (C8 - 1);            // idx % 16
    unsigned t  = (idx >> 4) & (T_DIM - 1);  // (idx / 16) % 4096
    unsigned b  = idx >> 16;                 // idx / (16*4096)

    int s = shifts[b] - MAX_SHIFT;           // [-409, 409]
    int src = (int)t - s;                    // [-409, 4504]
    if (src < 0)           src += T_DIM;
    else if (src >= T_DIM) src -= T_DIM;

    // element offsets (floats)
    unsigned src_off = (b << 19) + ((unsigned)src << 7) + (c8 << 3);
    unsigned dst_off = idx << 3;

    float xv[8], nv[8];
    ldg256_cs(x + src_off, xv);
    ldg256_cs(noise + src_off, nv);
    float sc = __ldg(&scale[b]);

    float o[8];
    #pragma unroll
    for (int i = 0; i < 8; i++)
        o[i] = fmaf(nv[i], NOISE_STD, xv[i]) * sc;

    stg256_cs(out + dst_off, o);
}

extern "C" void kernel_launch(void* const* d_in, const int* in_sizes, int n_in,
                              void* d_out, int out_size)
{
    const float* x      = (const float*)d_in[0];
    const float* noise  = (const float*)d_in[1];
    const float* scale  = (const float*)d_in[2];
    const int*   shifts = (const int*)d_in[3];
    float* out = (float*)d_out;

    const unsigned total = B_DIM * T_DIM * C8;   // 4,194,304
    const unsigned blocks = total / THREADS;     // 16384

    ts_augment_kernel<<<blocks, THREADS>>>(x, noise, scale, shifts, out);
}

// round 7
// speedup vs baseline: 1.0041x; 1.0041x over previous
#include <cuda_runtime.h>
#include <cuda_bf16.h>

// out[b,t,c] = (x[b,src,c] + noise[b,src,c]*0.1f) * scale[b]
// src = (t - (shifts[b] - MAX_SHIFT)) mod T
// B=64, T=4096, C=128, fp32. HBM-streaming at the achieved-BW ceiling:
// 256-bit (v8.f32) accesses, .cs streaming hints, 512-thread blocks.

#define B_DIM 64
#define T_DIM 4096
#define C_DIM 128
#define MAX_SHIFT 409
#define NOISE_STD 0.1f

#define C8 (C_DIM / 8)   // 16 v8-groups per (b,t) row
#define THREADS 512

__device__ __forceinline__ void ldg256_cs(const float* p, float v[8]) {
    // non-volatile: outputs keep it live, scheduler may reorder freely
    asm("ld.global.cs.v8.f32 {%0,%1,%2,%3,%4,%5,%6,%7}, [%8];"
        : "=f"(v[0]), "=f"(v[1]), "=f"(v[2]), "=f"(v[3]),
          "=f"(v[4]), "=f"(v[5]), "=f"(v[6]), "=f"(v[7])
        : "l"(p));
}

__device__ __forceinline__ void stg256_cs(float* p, const float v[8]) {
    asm volatile("st.global.cs.v8.f32 [%0], {%1,%2,%3,%4,%5,%6,%7,%8};"
                 :: "l"(p),
                    "f"(v[0]), "f"(v[1]), "f"(v[2]), "f"(v[3]),
                    "f"(v[4]), "f"(v[5]), "f"(v[6]), "f"(v[7])
                 : "memory");
}

__global__ __launch_bounds__(THREADS)
void ts_augment_kernel(const float* __restrict__ x,
                       const float* __restrict__ noise,
                       const float* __restrict__ scale,
                       const int*   __restrict__ shifts,
                       float*       __restrict__ out)
{
    // flat index over B * T * C8 = 4,194,304; grid*block covers exactly.
    unsigned idx = blockIdx.x * blockDim.x + threadIdx.x;
    unsigned c8 = idx & (C8 - 1);            // idx % 16
    unsigned t  = (idx >> 4) & (T_DIM - 1);  // (idx / 16) % 4096
    unsigned b  = idx >> 16;                 // idx / (16*4096)

    int s = shifts[b] - MAX_SHIFT;           // [-409, 409]
    int src = (int)t - s;                    // [-409, 4504]
    if (src < 0)           src += T_DIM;
    else if (src >= T_DIM) src -= T_DIM;

    // element offsets (floats)
    unsigned src_off = (b << 19) + ((unsigned)src << 7) + (c8 << 3);
    unsigned dst_off = idx << 3;

    float xv[8], nv[8];
    ldg256_cs(x + src_off, xv);
    ldg256_cs(noise + src_off, nv);

    float sc  = __ldg(&scale[b]);
    float nsc = sc * NOISE_STD;   // out = x*sc + noise*(0.1*sc): two independent muls -> 1 MUL + 1 FMA each

    float o[8];
    #pragma unroll
    for (int i = 0; i < 8; i++)
        o[i] = fmaf(nv[i], nsc, xv[i] * sc);

    stg256_cs(out + dst_off, o);
}

extern "C" void kernel_launch(void* const* d_in, const int* in_sizes, int n_in,
                              void* d_out, int out_size)
{
    const float* x      = (const float*)d_in[0];
    const float* noise  = (const float*)d_in[1];
    const float* scale  = (const float*)d_in[2];
    const int*   shifts = (const int*)d_in[3];
    float* out = (float*)d_out;

    const unsigned total = B_DIM * T_DIM * C8;   // 4,194,304
    const unsigned blocks = total / THREADS;     // 8192

    ts_augment_kernel<<<blocks, THREADS>>>(x, noise, scale, shifts, out);
}

// round 8
// speedup vs baseline: 1.0114x; 1.0073x over previous
#include <cuda_runtime.h>
#include <cuda_bf16.h>

// out[b,t,c] = (x[b,src,c] + noise[b,src,c]*0.1f) * scale[b]
// src = (t - (shifts[b] - MAX_SHIFT)) mod T
// B=64, T=4096, C=128, fp32.
// Sustained-mode (graph-replay) winner family: float4 + .cs streaming hints.
// This round: + 512-thread blocks, + hoisted scale FMA.

#define B_DIM 64
#define T_DIM 4096
#define C_DIM 128
#define MAX_SHIFT 409
#define NOISE_STD 0.1f

#define C4 (C_DIM / 4)   // 32 float4 per (b,t) row
#define THREADS 512

__global__ __launch_bounds__(THREADS)
void ts_augment_kernel(const float4* __restrict__ x,
                       const float4* __restrict__ noise,
                       const float*  __restrict__ scale,
                       const int*    __restrict__ shifts,
                       float4*       __restrict__ out)
{
    // flat index over B * T * C4 = 8,388,608; grid*block covers exactly.
    unsigned idx = blockIdx.x * blockDim.x + threadIdx.x;
    unsigned c4 = idx & (C4 - 1);            // idx % 32
    unsigned t  = (idx >> 5) & (T_DIM - 1);  // (idx / 32) % 4096
    unsigned b  = idx >> 17;                 // idx / (32*4096)

    int s = shifts[b] - MAX_SHIFT;           // [-409, 409]
    int src = (int)t - s;                    // [-409, 4504]
    if (src < 0)           src += T_DIM;
    else if (src >= T_DIM) src -= T_DIM;

    unsigned src_idx = (b << 17) + ((unsigned)src << 5) + c4;

    // Touch-once streams: evict-first reads, streaming store.
    float4 xv = __ldcs(&x[src_idx]);
    float4 nv = __ldcs(&noise[src_idx]);

    float sc  = __ldg(&scale[b]);
    float nsc = sc * NOISE_STD;   // out = x*sc + n*(0.1*sc): independent MUL + FMA per lane

    float4 o;
    o.x = fmaf(nv.x, nsc, xv.x * sc);
    o.y = fmaf(nv.y, nsc, xv.y * sc);
    o.z = fmaf(nv.z, nsc, xv.z * sc);
    o.w = fmaf(nv.w, nsc, xv.w * sc);

    __stcs(&out[idx], o);
}

extern "C" void kernel_launch(void* const* d_in, const int* in_sizes, int n_in,
                              void* d_out, int out_size)
{
    const float4* x      = (const float4*)d_in[0];
    const float4* noise  = (const float4*)d_in[1];
    const float*  scale  = (const float*)d_in[2];
    const int*    shifts = (const int*)d_in[3];
    float4* out = (float4*)d_out;

    const unsigned total = B_DIM * T_DIM * C4;   // 8,388,608
    const unsigned blocks = total / THREADS;     // 16384

    ts_augment_kernel<<<blocks, THREADS>>>(x, noise, scale, shifts, out);
}

// round 9
// speedup vs baseline: 1.0390x; 1.0273x over previous
#include <cuda_runtime.h>
#include <cuda_bf16.h>

// out[b,t,c] = (x[b,src,c] + noise[b,src,c]*0.1f) * scale[b]
// src = (t - (shifts[b] - MAX_SHIFT)) mod T
// B=64, T=4096, C=128, fp32.
// Best sustained-mode config (R3): float4 + .cs streaming hints + 256-thread
// blocks, occ ~81%. This round: identical config + hoisted scale (free FLOP cut).

#define B_DIM 64
#define T_DIM 4096
#define C_DIM 128
#define MAX_SHIFT 409
#define NOISE_STD 0.1f

#define C4 (C_DIM / 4)   // 32 float4 per (b,t) row
#define THREADS 256

__global__ __launch_bounds__(THREADS)
void ts_augment_kernel(const float4* __restrict__ x,
                       const float4* __restrict__ noise,
                       const float*  __restrict__ scale,
                       const int*    __restrict__ shifts,
                       float4*       __restrict__ out)
{
    // flat index over B * T * C4 = 8,388,608; grid*block covers exactly.
    unsigned idx = blockIdx.x * blockDim.x + threadIdx.x;
    unsigned c4 = idx & (C4 - 1);            // idx % 32
    unsigned t  = (idx >> 5) & (T_DIM - 1);  // (idx / 32) % 4096
    unsigned b  = idx >> 17;                 // idx / (32*4096)

    int s = shifts[b] - MAX_SHIFT;           // [-409, 409]
    int src = (int)t - s;                    // [-409, 4504]
    if (src < 0)           src += T_DIM;
    else if (src >= T_DIM) src -= T_DIM;

    unsigned src_idx = (b << 17) + ((unsigned)src << 5) + c4;

    // Touch-once streams: evict-first reads, streaming store.
    float4 xv = __ldcs(&x[src_idx]);
    float4 nv = __ldcs(&noise[src_idx]);

    float sc  = __ldg(&scale[b]);
    float nsc = sc * NOISE_STD;   // out = x*sc + n*(0.1*sc): independent MUL + FMA per lane

    float4 o;
    o.x = fmaf(nv.x, nsc, xv.x * sc);
    o.y = fmaf(nv.y, nsc, xv.y * sc);
    o.z = fmaf(nv.z, nsc, xv.z * sc);
    o.w = fmaf(nv.w, nsc, xv.w * sc);

    __stcs(&out[idx], o);
}

extern "C" void kernel_launch(void* const* d_in, const int* in_sizes, int n_in,
                              void* d_out, int out_size)
{
    const float4* x      = (const float4*)d_in[0];
    const float4* noise  = (const float4*)d_in[1];
    const float*  scale  = (const float*)d_in[2];
    const int*    shifts = (const int*)d_in[3];
    float4* out = (float4*)d_out;

    const unsigned total = B_DIM * T_DIM * C4;   // 8,388,608
    const unsigned blocks = total / THREADS;     // 32768

    ts_augment_kernel<<<blocks, THREADS>>>(x, noise, scale, shifts, out);
}